// round 7
// baseline (speedup 1.0000x reference)
#include <cuda_runtime.h>
#include <math.h>

#define NELEM  16384
#define KSEL   8192
#define NCTA   16
#define NT     1024
#define CPB    1024
#define NBINS  16384
#define SH     12
#define LOBITS 0x3B800000u   // float bits of 2^-8; lower scores clamp to bin 0

// ---- persistent scratch (zero-init at load; self-maintained across replays) ----
__device__ __align__(16) unsigned int g_hist[NBINS];  // re-zeroed by CTA0 (sole reader) each launch
__device__ uint2        g_cand[NELEM];
__device__ unsigned int g_payload[2];
__device__ unsigned int g_seq;      // monotonic publication counter (+1 per launch)
__device__ unsigned int g_arrive;   // monotonic arrival counter (+NCTA per launch)
__device__ unsigned int g_ticket;   // reset each launch inside CTA0's exclusive window
__device__ unsigned int g_done;     // reset each launch inside CTA0's exclusive window

__device__ __forceinline__ unsigned int ld_acq(const unsigned int* p) {
    unsigned int v;
    asm volatile("ld.acquire.gpu.u32 %0, [%1];" : "=r"(v) : "l"(p) : "memory");
    return v;
}
__device__ __forceinline__ unsigned int ld_rlx(const unsigned int* p) {
    unsigned int v;
    asm volatile("ld.relaxed.gpu.u32 %0, [%1];" : "=r"(v) : "l"(p) : "memory");
    return v;
}
__device__ __forceinline__ void red_rel_add(unsigned int* p, unsigned int v) {
    asm volatile("red.release.gpu.global.add.u32 [%0], %1;" :: "l"(p), "r"(v) : "memory");
}

__global__ __launch_bounds__(NT, 1)
void connect_attention_flag(const float* __restrict__ x,
                            const float* __restrict__ w7,
                            float* __restrict__ out)
{
    __shared__ float        sx[CPB + 6];
    __shared__ unsigned int sm_w[32];
    __shared__ unsigned int s_seq, s_w0, s_w1;

    const int tid  = threadIdx.x;
    const int lane = tid & 31;
    const int wid  = tid >> 5;
    const int E0   = (int)blockIdx.x * CPB;
    const int gid  = E0 + tid;

    // capture the sequence number BEFORE this launch's publication can happen
    // (publication requires this CTA's own arrival, which comes later)
    if (tid == 0) s_seq = ld_rlx(&g_seq);

    // ---- stage x tile (+3 halo each side) ----
    sx[3 + tid] = __ldg(x + gid);
    if (tid < 3) {
        const int gl = E0 - 3 + tid;
        sx[tid] = (gl >= 0) ? __ldg(x + gl) : 0.0f;
        const int gr = E0 + CPB + tid;
        sx[3 + CPB + tid] = (gr < NELEM) ? __ldg(x + gr) : 0.0f;
    }
    const float w0 = __ldg(w7 + 0), w1 = __ldg(w7 + 1), w2 = __ldg(w7 + 2),
                w3 = __ldg(w7 + 3), w4 = __ldg(w7 + 4), w5 = __ldg(w7 + 5),
                w6 = __ldg(w7 + 6);
    __syncthreads();

    // ---- conv 'same' + sigmoid ----
    const float xi = sx[3 + tid];
    float y = sx[tid] * w0;
    y = fmaf(sx[tid + 1], w1, y);
    y = fmaf(sx[tid + 2], w2, y);
    y = fmaf(xi,          w3, y);
    y = fmaf(sx[tid + 4], w4, y);
    y = fmaf(sx[tid + 5], w5, y);
    y = fmaf(sx[tid + 6], w6, y);
    const float s = 1.0f / (1.0f + expf(-y));
    out[NELEM + gid] = s;                        // attention_score output

    const unsigned int v = __float_as_uint(s);   // positive: bit order == value order
    const int d   = (int)(v - LOBITS);
    const int bin = d < 0 ? 0 : (d >> SH);       // < NBINS (s < 1.0)

    atomicAdd(&g_hist[bin], 1u);                 // RED (result unused)

    __syncthreads();                             // all this CTA's REDs issued
    if (tid == 0) {
        __threadfence();                         // REDs visible before arrival
        red_rel_add(&g_arrive, 1u);
    }

    if (blockIdx.x == 0) {
        // ======== CTA0: sole histogram consumer ========
        if (tid == 0) {
            const unsigned int target = (unsigned int)NCTA * (s_seq + 1u);
            while (ld_acq(&g_arrive) < target) { }
            // exclusive window (no registrant acts before publication)
            g_ticket = 0u;
            g_done   = 0u;
        }
        __syncthreads();

        // scan 16384 bins, 16/thread
        unsigned int h[16];
        {
            const uint4* hp = (const uint4*)(g_hist + tid * 16);
            uint4 q0 = __ldcg(hp + 0), q1 = __ldcg(hp + 1),
                  q2 = __ldcg(hp + 2), q3 = __ldcg(hp + 3);
            h[0]=q0.x; h[1]=q0.y; h[2]=q0.z; h[3]=q0.w;
            h[4]=q1.x; h[5]=q1.y; h[6]=q1.z; h[7]=q1.w;
            h[8]=q2.x; h[9]=q2.y; h[10]=q2.z; h[11]=q2.w;
            h[12]=q3.x; h[13]=q3.y; h[14]=q3.z; h[15]=q3.w;
        }
        unsigned int local = 0;
        #pragma unroll
        for (int q = 0; q < 16; ++q) local += h[q];

        unsigned int inc = local;
        #pragma unroll
        for (int o = 1; o < 32; o <<= 1) {
            unsigned int t = __shfl_up_sync(0xffffffffu, inc, o);
            if (lane >= o) inc += t;
        }
        if (lane == 31) sm_w[wid] = inc;
        __syncthreads();
        if (wid == 0) {
            unsigned int wsum = sm_w[lane];
            unsigned int winc = wsum;
            #pragma unroll
            for (int o = 1; o < 32; o <<= 1) {
                unsigned int t = __shfl_up_sync(0xffffffffu, winc, o);
                if (lane >= o) winc += t;
            }
            sm_w[lane] = winc - wsum;            // exclusive warp base
        }
        __syncthreads();
        const unsigned int base = sm_w[wid] + inc - local;

        if (base < KSEL && base + local >= KSEL) {   // exactly one thread
            unsigned int c = base;
            #pragma unroll
            for (int q = 0; q < 16; ++q) {
                if (c + h[q] >= KSEL) {
                    const unsigned int bst = (unsigned int)(tid * 16 + q);
                    s_w0 = bst | ((KSEL - c) << 16);   // bstar | (jkeep<<16)
                    s_w1 = h[q];                        // hcount
                    break;
                }
                c += h[q];
            }
        }
        __syncthreads();

        if (tid == 0) {
            g_payload[0] = s_w0;
            g_payload[1] = s_w1;
            __threadfence();
            red_rel_add(&g_seq, 1u);             // publish
        }

        // re-zero hist for next replay (sole reader; values already in regs)
        {
            const uint4 z = make_uint4(0u, 0u, 0u, 0u);
            uint4* hz = (uint4*)(g_hist + tid * 16);
            hz[0] = z; hz[1] = z; hz[2] = z; hz[3] = z;
        }
    } else {
        // ======== other CTAs: wait on the single publication line ========
        if (tid == 0) {
            const unsigned int want = s_seq + 1u;
            while (ld_acq(&g_seq) < want) { }
            s_w0 = __ldcg(&g_payload[0]);
            s_w1 = __ldcg(&g_payload[1]);
        }
        __syncthreads();
    }

    const int          bstar  = (int)(s_w0 & 0xFFFFu);
    const unsigned int jkeep  = s_w0 >> 16;
    const unsigned int hcount = s_w1;

    // ---- emit ----
    if (bin != bstar) {
        out[gid] = (bin < bstar) ? xi * (s + 1.0f) : 0.0f;
    } else {
        // register, then wait for exactly hcount registrations (known a priori)
        const unsigned int t = atomicAdd(&g_ticket, 1u);
        g_cand[t] = make_uint2(v, (unsigned int)gid);
        red_rel_add(&g_done, 1u);
        while (ld_acq(&g_done) < hcount) { }
        unsigned int rank = 0;
        for (unsigned int c = 0; c < hcount; ++c) {
            const uint2 cd = __ldcg(&g_cand[c]);
            rank += (cd.x < v) || (cd.x == v && cd.y < (unsigned int)gid);
        }
        out[gid] = (rank < jkeep) ? xi * (s + 1.0f) : 0.0f;
    }
}

extern "C" void kernel_launch(void* const* d_in, const int* in_sizes, int n_in,
                              void* d_out, int out_size)
{
    const float* x = (const float*)d_in[0];
    const float* w = (const float*)d_in[1];
    if (n_in >= 2 && in_sizes[0] == 7) {   // defensive input-order check
        const float* t = x; x = w; w = t;
    }
    float* out = (float*)d_out;

    connect_attention_flag<<<NCTA, NT>>>(x, w, out);
}

// round 8
// speedup vs baseline: 1.2948x; 1.2948x over previous
#include <cuda_runtime.h>
#include <math.h>

#define NELEM  16384
#define KSEL   8192
#define NB     8        // CTAs == cluster size (one CGA spans the grid)
#define NT     1024
#define CPB    2048     // contiguous elements per CTA
#define NBINS  16384
#define SH     12
#define LOBITS 0x3B800000u   // float bits of 2^-8; lower scores clamp to bin 0

// ---- persistent scratch (zero-init at load; maintained across graph replays) ----
// Histogram is double-buffered by launch parity: launch L uses buffer p=L&1 and
// zeroes buffer p^1 (+ its ticket/done counters) for launch L+1. Launches are
// stream-serialized, so cross-launch ordering comes free from the launch boundary.
__device__ __align__(16) unsigned int g_hist[2][NBINS];
__device__ uint2        g_cand[NELEM];
__device__ unsigned int g_ticket[2];
__device__ unsigned int g_done[2];
__device__ unsigned int g_launch;    // monotonic; parity source

__device__ __forceinline__ unsigned int ld_acq(const unsigned int* p) {
    unsigned int v;
    asm volatile("ld.acquire.gpu.u32 %0, [%1];" : "=r"(v) : "l"(p) : "memory");
    return v;
}
__device__ __forceinline__ void red_rel_add(unsigned int* p, unsigned int v) {
    asm volatile("red.release.gpu.global.add.u32 [%0], %1;" :: "l"(p), "r"(v) : "memory");
}

// HW cluster barrier; arrive has cluster-scope release semantics, so prior gmem
// writes by cluster threads are visible to cluster peers after the wait.
__device__ __forceinline__ void cbar()
{
    asm volatile("barrier.cluster.arrive.aligned;" ::: "memory");
    asm volatile("barrier.cluster.wait.aligned;"   ::: "memory");
}

__global__ __launch_bounds__(NT, 1) __cluster_dims__(NB, 1, 1)
void connect_attention_cga3(const float* __restrict__ x,
                            const float* __restrict__ w7,
                            float* __restrict__ out)
{
    __shared__ float        sx[CPB + 6];     // x[E0-3 .. E0+CPB+2]
    __shared__ float        swt[7];
    __shared__ unsigned int sm_w[32];
    __shared__ unsigned int s_par, s_w0, s_w1;

    const int tid  = threadIdx.x;
    const int lane = tid & 31;
    const int wid  = tid >> 5;
    const int E0   = (int)blockIdx.x * CPB;
    const int l0   = 2 * tid;
    const int e0   = E0 + l0;

    // launch parity (all CTAs of one launch agree: tickets are 8L..8L+7)
    if (tid == 0) s_par = (atomicAdd(&g_launch, 1u) / NB) & 1u;
    if (tid < 7)  swt[tid] = __ldg(w7 + tid);

    // ---- stage x tile (+halo) into smem ----
    {
        const float2 xv = *(const float2*)(x + e0);
        sx[3 + l0]     = xv.x;
        sx[3 + l0 + 1] = xv.y;
        if (tid < 3) {
            const int gl = E0 - 3 + tid;
            sx[tid] = (gl >= 0) ? __ldg(x + gl) : 0.0f;
            const int gr = E0 + CPB + tid;
            sx[3 + CPB + tid] = (gr < NELEM) ? __ldg(x + gr) : 0.0f;
        }
    }
    __syncthreads();
    const unsigned int par = s_par;

    // zero the OTHER hist buffer + its counters for the next launch (unordered:
    // nothing touches buffer par^1 during this launch)
    {
        uint2* hz = (uint2*)g_hist[par ^ 1u];
        hz[(int)blockIdx.x * NT + tid] = make_uint2(0u, 0u);   // 8192 threads x 2 bins
        if (tid == 0 && blockIdx.x == 0) {
            g_ticket[par ^ 1u] = 0u;
            g_done[par ^ 1u]   = 0u;
        }
    }

    const float w0 = swt[0], w1 = swt[1], w2 = swt[2], w3 = swt[3],
                w4 = swt[4], w5 = swt[5], w6 = swt[6];

    // ---- conv 'same' + sigmoid for elems e0, e0+1 ----
    const float a0 = sx[l0],     a1 = sx[l0 + 1], a2 = sx[l0 + 2], a3 = sx[l0 + 3],
                a4 = sx[l0 + 4], a5 = sx[l0 + 5], a6 = sx[l0 + 6], a7 = sx[l0 + 7];

    float y0 = a0 * w0;
    y0 = fmaf(a1, w1, y0); y0 = fmaf(a2, w2, y0); y0 = fmaf(a3, w3, y0);
    y0 = fmaf(a4, w4, y0); y0 = fmaf(a5, w5, y0); y0 = fmaf(a6, w6, y0);
    float y1 = a1 * w0;
    y1 = fmaf(a2, w1, y1); y1 = fmaf(a3, w2, y1); y1 = fmaf(a4, w3, y1);
    y1 = fmaf(a5, w4, y1); y1 = fmaf(a6, w5, y1); y1 = fmaf(a7, w6, y1);

    const float s0 = 1.0f / (1.0f + expf(-y0));
    const float s1 = 1.0f / (1.0f + expf(-y1));
    *(float2*)(out + NELEM + e0) = make_float2(s0, s1);   // attention_score

    const unsigned int v0 = __float_as_uint(s0);   // positive: bit order == value order
    const unsigned int v1 = __float_as_uint(s1);
    const int d0 = (int)(v0 - LOBITS);
    const int d1 = (int)(v1 - LOBITS);
    const int bin0 = d0 < 0 ? 0 : (d0 >> SH);      // < NBINS (s < 1.0)
    const int bin1 = d1 < 0 ? 0 : (d1 >> SH);

    unsigned int* hist = g_hist[par];
    if (bin0 == bin1) {
        atomicAdd(&hist[bin0], 2u);
    } else {
        atomicAdd(&hist[bin0], 1u);
        atomicAdd(&hist[bin1], 1u);
    }

    cbar();   // ---- THE single grid edge: histogram complete ----

    // ---- redundant per-CTA prefix scan over 16384 bins (16/thread) ----
    {
        unsigned int h[16];
        {
            const uint4* hp = (const uint4*)(hist + tid * 16);
            uint4 q0 = __ldcg(hp + 0), q1 = __ldcg(hp + 1),
                  q2 = __ldcg(hp + 2), q3 = __ldcg(hp + 3);
            h[0]=q0.x; h[1]=q0.y; h[2]=q0.z; h[3]=q0.w;
            h[4]=q1.x; h[5]=q1.y; h[6]=q1.z; h[7]=q1.w;
            h[8]=q2.x; h[9]=q2.y; h[10]=q2.z; h[11]=q2.w;
            h[12]=q3.x; h[13]=q3.y; h[14]=q3.z; h[15]=q3.w;
        }
        unsigned int local = 0;
        #pragma unroll
        for (int q = 0; q < 16; ++q) local += h[q];

        unsigned int inc = local;
        #pragma unroll
        for (int o = 1; o < 32; o <<= 1) {
            unsigned int t = __shfl_up_sync(0xffffffffu, inc, o);
            if (lane >= o) inc += t;
        }
        if (lane == 31) sm_w[wid] = inc;
        __syncthreads();
        if (wid == 0) {
            unsigned int wsum = sm_w[lane];
            unsigned int winc = wsum;
            #pragma unroll
            for (int o = 1; o < 32; o <<= 1) {
                unsigned int t = __shfl_up_sync(0xffffffffu, winc, o);
                if (lane >= o) winc += t;
            }
            sm_w[lane] = winc - wsum;    // exclusive warp base
        }
        __syncthreads();
        const unsigned int base = sm_w[wid] + inc - local;

        if (base < KSEL && base + local >= KSEL) {   // exactly one thread
            unsigned int c = base;
            #pragma unroll
            for (int q = 0; q < 16; ++q) {
                if (c + h[q] >= KSEL) {
                    s_w0 = (unsigned)(tid * 16 + q) | ((KSEL - c) << 16);  // bstar | jkeep<<16
                    s_w1 = h[q];                                            // hcount
                    break;
                }
                c += h[q];
            }
        }
    }
    __syncthreads();
    const int          bstar  = (int)(s_w0 & 0xFFFFu);
    const unsigned int jkeep  = s_w0 >> 16;
    const unsigned int hcount = s_w1;

    // ---- fast path: non-boundary elements emit immediately, no further sync ----
    const bool b0 = (bin0 == bstar);
    const bool b1 = (bin1 == bstar);

    float o0 = (bin0 < bstar) ? a3 * (s0 + 1.0f) : 0.0f;   // a3 == x[e0]
    float o1 = (bin1 < bstar) ? a4 * (s1 + 1.0f) : 0.0f;   // a4 == x[e0+1]

    if (b0 | b1) {
        // register all owned boundary elems, then spin until all hcount are in
        if (b0) {
            unsigned int t = atomicAdd(&g_ticket[par], 1u);
            g_cand[t] = make_uint2(v0, (unsigned)e0);
        }
        if (b1) {
            unsigned int t = atomicAdd(&g_ticket[par], 1u);
            g_cand[t] = make_uint2(v1, (unsigned)(e0 + 1));
        }
        red_rel_add(&g_done[par], (unsigned)b0 + (unsigned)b1);
        while (ld_acq(&g_done[par]) < hcount) { }

        unsigned int r0 = 0, r1 = 0;
        for (unsigned int c = 0; c < hcount; ++c) {
            const uint2 cd = __ldcg(&g_cand[c]);
            r0 += (cd.x < v0) || (cd.x == v0 && cd.y < (unsigned)e0);
            r1 += (cd.x < v1) || (cd.x == v1 && cd.y < (unsigned)(e0 + 1));
        }
        if (b0) o0 = (r0 < jkeep) ? a3 * (s0 + 1.0f) : 0.0f;
        if (b1) o1 = (r1 < jkeep) ? a4 * (s1 + 1.0f) : 0.0f;
    }
    *(float2*)(out + e0) = make_float2(o0, o1);
}

extern "C" void kernel_launch(void* const* d_in, const int* in_sizes, int n_in,
                              void* d_out, int out_size)
{
    const float* x = (const float*)d_in[0];
    const float* w = (const float*)d_in[1];
    if (n_in >= 2 && in_sizes[0] == 7) {   // defensive input-order check
        const float* t = x; x = w; w = t;
    }
    float* out = (float*)d_out;

    connect_attention_cga3<<<NB, NT>>>(x, w, out);
}